// round 2
// baseline (speedup 1.0000x reference)
#include <cuda_runtime.h>
#include <math.h>

// Problem constants
#define Bn 16
#define Nn 256
#define Fn 64
#define Hn 128

// Table constants
#define Tn 512
#define D_MAX 1.7320509f

// Scratch: per-feature univariate function table g_f(d), built per launch.
__device__ float g_table[Tn * Fn];

__device__ __forceinline__ float softplus_acc(float x) {
    // matches jax.nn.softplus = logaddexp(x, 0), stable for all x
    return fmaxf(x, 0.0f) + log1pf(expf(-fabsf(x)));
}

// ---------------------------------------------------------------------------
// Kernel 1: build g_table[k][f] = softplus( sum_h softplus(d_k*w1+b1)*W2[h,f] + b2[f] )
// grid = Tn blocks, block = Hn threads.
// ---------------------------------------------------------------------------
__global__ void build_table_kernel(const float* __restrict__ w1,
                                   const float* __restrict__ b1,
                                   const float* __restrict__ W2,
                                   const float* __restrict__ b2) {
    __shared__ float u[Hn];
    const int k = blockIdx.x;
    const int h = threadIdx.x;  // 0..127
    const float d = (float)k * (D_MAX / (float)(Tn - 1));
    u[h] = softplus_acc(fmaf(d, w1[h], b1[h]));
    __syncthreads();
    if (h < Fn) {
        float acc = b2[h];
#pragma unroll
        for (int hh = 0; hh < Hn; ++hh)
            acc = fmaf(u[hh], W2[hh * Fn + h], acc);
        g_table[k * Fn + h] = softplus_acc(acc);
    }
}

// ---------------------------------------------------------------------------
// Kernel 2: main reduction.
// grid = 128 CTAs (one per 32 output rows), block = 512 threads (16 warps).
// Thread (fg = (tid&15)*4, il = tid>>4) owns features [fg,fg+4) of row
// 32*cta + il. Within a warp, f-tile and distance loads are 2-way broadcast
// (free), so effective LDS bytes match the 256-thread version while warp
// parallelism doubles.
// ---------------------------------------------------------------------------
#define DROW 257  // padded row stride for distance tile (avoid bank conflicts)

__global__ void __launch_bounds__(512, 1)
mp_main_kernel(const float* __restrict__ r, const float* __restrict__ f,
               float* __restrict__ out) {
    extern __shared__ float sm[];
    float* tab = sm;                    // Tn*Fn   = 32768 floats (128 KB)
    float* fsm = tab + Tn * Fn;         // Nn*Fn   = 16384 floats (64 KB)
    float* dsm = fsm + Nn * Fn;         // 32*DROW =  8224 floats (~32 KB)

    const int tid = threadIdx.x;
    const int cta = blockIdx.x;             // 0..127
    const int b = cta >> 3;                 // 8 CTAs per batch element
    const int i0_local = (cta & 7) * 32;    // first local row of this tile

    // 1) stage r[b] (256x3 floats) into the f-tile area temporarily
    for (int e = tid; e < Nn * 3; e += 512)
        fsm[e] = r[b * Nn * 3 + e];
    __syncthreads();

    // 2) pre-scaled distances for the 32 tile rows vs all 256 j
    const float scale = (float)(Tn - 1) / D_MAX;
    for (int e = tid; e < 32 * Nn; e += 512) {
        const int il = e >> 8;
        const int j = e & 255;
        const int ig = i0_local + il;
        const float dx = fsm[ig * 3 + 0] - fsm[j * 3 + 0];
        const float dy = fsm[ig * 3 + 1] - fsm[j * 3 + 1];
        const float dz = fsm[ig * 3 + 2] - fsm[j * 3 + 2];
        const float s = fmaf(dx, dx, fmaf(dy, dy, dz * dz));
        float d;
        asm("sqrt.approx.f32 %0, %1;" : "=f"(d) : "f"(s));  // sqrt.approx(0)=0
        dsm[il * DROW + j] = d * scale;
    }
    __syncthreads();

    // 3) stage f[b] tile and the interpolation table (overwrites r staging)
    for (int e = tid; e < (Nn * Fn) / 4; e += 512)
        ((float4*)fsm)[e] = ((const float4*)(f + b * Nn * Fn))[e];
    for (int e = tid; e < (Tn * Fn) / 4; e += 512)
        ((float4*)tab)[e] = ((const float4*)g_table)[e];
    __syncthreads();

    // 4) main loop over j — 1 row, 4 features per thread
    const int fg = (tid & 15) * 4;  // feature offset (0,4,...,60)
    const int il = tid >> 4;        // local row 0..31
    const float* drow = dsm + il * DROW;
    const float* fjp = fsm + fg;
    const float* tabp = tab + fg;

    float4 acc = make_float4(0.f, 0.f, 0.f, 0.f);

#pragma unroll 8
    for (int j = 0; j < Nn; ++j) {
        const float u = drow[j];
        const float4 fv = *(const float4*)(fjp + j * Fn);

        int k = (int)u; k = min(k, Tn - 2);
        const float t = u - (float)k;

        const float4 a = *(const float4*)(tabp + k * Fn);
        const float4 c = *(const float4*)(tabp + (k + 1) * Fn);

        float g;
        g = fmaf(t, c.x - a.x, a.x); acc.x = fmaf(g, fv.x, acc.x);
        g = fmaf(t, c.y - a.y, a.y); acc.y = fmaf(g, fv.y, acc.y);
        g = fmaf(t, c.z - a.z, a.z); acc.z = fmaf(g, fv.z, acc.z);
        g = fmaf(t, c.w - a.w, a.w); acc.w = fmaf(g, fv.w, acc.w);
    }

    // 5) final softplus + store
    const int row = cta * 32 + il;  // global row index (b*N + i)
    float4 o;
    o.x = softplus_acc(acc.x); o.y = softplus_acc(acc.y);
    o.z = softplus_acc(acc.z); o.w = softplus_acc(acc.w);
    *(float4*)(out + row * Fn + fg) = o;
}

// ---------------------------------------------------------------------------
extern "C" void kernel_launch(void* const* d_in, const int* in_sizes, int n_in,
                              void* d_out, int out_size) {
    const float* r_batch = (const float*)d_in[0];  // [16,256,3]
    const float* f_batch = (const float*)d_in[1];  // [16,256,64]
    const float* w1 = (const float*)d_in[2];       // [128]
    const float* b1 = (const float*)d_in[3];       // [128]
    const float* W2 = (const float*)d_in[4];       // [128,64]
    const float* b2 = (const float*)d_in[5];       // [64]
    float* out = (float*)d_out;                    // [16,256,64]

    build_table_kernel<<<Tn, Hn>>>(w1, b1, W2, b2);

    const int smem_bytes = (Tn * Fn + Nn * Fn + 32 * DROW) * (int)sizeof(float);
    static bool attr_set = false;
    if (!attr_set) {
        cudaFuncSetAttribute(mp_main_kernel,
                             cudaFuncAttributeMaxDynamicSharedMemorySize,
                             smem_bytes);
        attr_set = true;
    }
    mp_main_kernel<<<(Bn * Nn) / 32, 512, smem_bytes>>>(r_batch, f_batch, out);
}

// round 3
// speedup vs baseline: 1.2605x; 1.2605x over previous
#include <cuda_runtime.h>
#include <cuda_fp16.h>
#include <math.h>

// Problem constants
#define Bn 16
#define Nn 256
#define Fn 64
#define Hn 128

// Table constants
#define Tn 512
#define D_MAX 1.7320509f
#define TROW 128  // bytes per table row: 64 features x half

// Scratch: half-precision table, 16B-aligned for vectorized copy.
__device__ uint4 g_table_raw[(Tn * Fn) / 8];

__device__ __forceinline__ float softplus_acc(float x) {
    // matches jax.nn.softplus = logaddexp(x, 0), stable for all x
    return fmaxf(x, 0.0f) + log1pf(expf(-fabsf(x)));
}

__device__ __forceinline__ __half2 u2h2(unsigned v) {
    return *reinterpret_cast<__half2*>(&v);
}

// ---------------------------------------------------------------------------
// Kernel 1: g_table[k][f] = softplus( sum_h softplus(d_k*w1+b1)*W2[h,f] + b2[f] )
// stored as half. grid = Tn blocks, block = Hn threads.
// ---------------------------------------------------------------------------
__global__ void build_table_kernel(const float* __restrict__ w1,
                                   const float* __restrict__ b1,
                                   const float* __restrict__ W2,
                                   const float* __restrict__ b2) {
    __shared__ float u[Hn];
    const int k = blockIdx.x;
    const int h = threadIdx.x;  // 0..127
    const float d = (float)k * (D_MAX / (float)(Tn - 1));
    u[h] = softplus_acc(fmaf(d, w1[h], b1[h]));
    __syncthreads();
    if (h < Fn) {
        float acc = b2[h];
#pragma unroll
        for (int hh = 0; hh < Hn; ++hh)
            acc = fmaf(u[hh], W2[hh * Fn + h], acc);
        ((__half*)g_table_raw)[k * Fn + h] = __float2half(softplus_acc(acc));
    }
}

// ---------------------------------------------------------------------------
// Kernel 2: main reduction.
// grid = 128 CTAs (32 output rows each), block = 256 threads.
// Thread (fg = tid&15, ip = tid>>4) owns features [4fg,4fg+4) of rows
// {32*cta + 2*ip, +1}. Warp covers 4 rows -> fv read amortized 4x.
// Table is half with 128B row pitch: lerp endpoints at addr and addr+128.
// (addr, t) precomputed per (row, j) in the staging pass.
// ---------------------------------------------------------------------------
__global__ void __launch_bounds__(256, 1)
mp_main_kernel(const float* __restrict__ r, const float* __restrict__ f,
               float* __restrict__ out) {
    extern __shared__ float sm[];
    __half* tab = (__half*)sm;            // 512*64 half  = 64 KB
    float* fsm = sm + 16384;              // 256*64 float = 64 KB
    int2* dsm = (int2*)(sm + 32768);      // 32*256 int2  = 64 KB

    const int tid = threadIdx.x;
    const int cta = blockIdx.x;             // 0..127
    const int b = cta >> 3;                 // 8 CTAs per batch element
    const int i0 = (cta & 7) * 32;          // first local row of this tile

    // 1) stage r[b] (256x3 floats) into the f-tile area temporarily
    for (int e = tid; e < Nn * 3; e += 256)
        fsm[e] = r[b * Nn * 3 + e];
    __syncthreads();

    // 2) precompute (table byte address, lerp t) for 32 rows x 256 j
    const float scale = (float)(Tn - 1) / D_MAX;
    for (int e = tid; e < 32 * Nn; e += 256) {
        const int il = e >> 8;
        const int j = e & 255;
        const int ig = i0 + il;
        const float dx = fsm[ig * 3 + 0] - fsm[j * 3 + 0];
        const float dy = fsm[ig * 3 + 1] - fsm[j * 3 + 1];
        const float dz = fsm[ig * 3 + 2] - fsm[j * 3 + 2];
        const float s = fmaf(dx, dx, fmaf(dy, dy, dz * dz));
        float d;
        asm("sqrt.approx.f32 %0, %1;" : "=f"(d) : "f"(s));  // sqrt.approx(0)=0
        const float uu = d * scale;
        int k = min((int)uu, Tn - 2);
        const float t = uu - (float)k;
        dsm[e] = make_int2(k * TROW, __float_as_int(t));
    }
    __syncthreads();

    // 3) stage f[b] tile and the half table (overwrites r staging)
    for (int e = tid; e < (Nn * Fn) / 4; e += 256)
        ((float4*)fsm)[e] = ((const float4*)(f + b * Nn * Fn))[e];
    for (int e = tid; e < (Tn * Fn) / 8; e += 256)
        ((uint4*)tab)[e] = g_table_raw[e];
    __syncthreads();

    // 4) main loop over j
    const int fg = tid & 15;        // feature group: features [4fg, 4fg+4)
    const int ip = tid >> 4;        // rows 2*ip, 2*ip+1
    const int2* dp0 = dsm + (2 * ip) * Nn;
    const int2* dp1 = dp0 + Nn;
    const char* tabc = (const char*)tab + fg * 8;  // 4 features x half
    const float* fjp = fsm + fg * 4;

    float4 acc0 = make_float4(0.f, 0.f, 0.f, 0.f);
    float4 acc1 = make_float4(0.f, 0.f, 0.f, 0.f);

#pragma unroll 4
    for (int j = 0; j < Nn; ++j) {
        const int2 at0 = dp0[j];
        const int2 at1 = dp1[j];
        const float4 fv = *(const float4*)(fjp + j * Fn);

        const char* p0 = tabc + at0.x;
        const char* p1 = tabc + at1.x;
        const uint2 a0 = *(const uint2*)(p0);
        const uint2 c0 = *(const uint2*)(p0 + TROW);
        const uint2 a1 = *(const uint2*)(p1);
        const uint2 c1 = *(const uint2*)(p1 + TROW);

        const __half2 t20 = __float2half2_rn(__int_as_float(at0.y));
        const __half2 t21 = __float2half2_rn(__int_as_float(at1.y));

        __half2 A, C, G;
        float2 gf;

        // row 0, features 0-1
        A = u2h2(a0.x); C = u2h2(c0.x);
        G = __hfma2(t20, __hsub2(C, A), A);
        gf = __half22float2(G);
        acc0.x = fmaf(gf.x, fv.x, acc0.x);
        acc0.y = fmaf(gf.y, fv.y, acc0.y);
        // row 0, features 2-3
        A = u2h2(a0.y); C = u2h2(c0.y);
        G = __hfma2(t20, __hsub2(C, A), A);
        gf = __half22float2(G);
        acc0.z = fmaf(gf.x, fv.z, acc0.z);
        acc0.w = fmaf(gf.y, fv.w, acc0.w);

        // row 1, features 0-1
        A = u2h2(a1.x); C = u2h2(c1.x);
        G = __hfma2(t21, __hsub2(C, A), A);
        gf = __half22float2(G);
        acc1.x = fmaf(gf.x, fv.x, acc1.x);
        acc1.y = fmaf(gf.y, fv.y, acc1.y);
        // row 1, features 2-3
        A = u2h2(a1.y); C = u2h2(c1.y);
        G = __hfma2(t21, __hsub2(C, A), A);
        gf = __half22float2(G);
        acc1.z = fmaf(gf.x, fv.z, acc1.z);
        acc1.w = fmaf(gf.y, fv.w, acc1.w);
    }

    // 5) final softplus + store
    const int row0 = cta * 32 + ip * 2;  // global row index (b*N + i)
    float4 o0, o1;
    o0.x = softplus_acc(acc0.x); o0.y = softplus_acc(acc0.y);
    o0.z = softplus_acc(acc0.z); o0.w = softplus_acc(acc0.w);
    o1.x = softplus_acc(acc1.x); o1.y = softplus_acc(acc1.y);
    o1.z = softplus_acc(acc1.z); o1.w = softplus_acc(acc1.w);
    *(float4*)(out + row0 * Fn + fg * 4) = o0;
    *(float4*)(out + (row0 + 1) * Fn + fg * 4) = o1;
}

// ---------------------------------------------------------------------------
extern "C" void kernel_launch(void* const* d_in, const int* in_sizes, int n_in,
                              void* d_out, int out_size) {
    const float* r_batch = (const float*)d_in[0];  // [16,256,3]
    const float* f_batch = (const float*)d_in[1];  // [16,256,64]
    const float* w1 = (const float*)d_in[2];       // [128]
    const float* b1 = (const float*)d_in[3];       // [128]
    const float* W2 = (const float*)d_in[4];       // [128,64]
    const float* b2 = (const float*)d_in[5];       // [64]
    float* out = (float*)d_out;                    // [16,256,64]

    build_table_kernel<<<Tn, Hn>>>(w1, b1, W2, b2);

    const int smem_bytes = 3 * 16384 * (int)sizeof(float);  // 192 KB
    static bool attr_set = false;
    if (!attr_set) {
        cudaFuncSetAttribute(mp_main_kernel,
                             cudaFuncAttributeMaxDynamicSharedMemorySize,
                             smem_bytes);
        attr_set = true;
    }
    mp_main_kernel<<<(Bn * Nn) / 32, 256, smem_bytes>>>(r_batch, f_batch, out);
}